// round 6
// baseline (speedup 1.0000x reference)
#include <cuda_runtime.h>
#include <math.h>

// CPPN fused MLP, fp32-faithful where it matters.
// R4 kernel, third submission (R4/R5 were broker infra failures; delta still
// unmeasured). Branch-free fast tanh (ex2.approx + NR-refined rcp.approx) for
// hidden layers 3..21 + sigmoid (late-layer noise amplification 1.4^(22-l)
// keeps the ~1.5e-7 injected error below the fp32 floor); accurate tanhf kept
// for layer1 + hidden 0..2 which carry ~93% of amplified error variance.
// Weights transposed k-major in shared, loaded as 16B LDS.128 broadcasts
// feeding packed FFMA2 (fma.rn.f32x2), 2 points/thread.

#define DH    32
#define NHID  22
#define NACC  3        // hidden layers using accurate tanhf
#define TPB   384
#define GRID  148
#define SWH_F (NHID * DH * DH)                   // 22528
#define SW1_F (11 * DH)                          // 352
#define SWO_F (DH * 4)                           // 128
#define SMEM_BYTES ((SWH_F + SW1_F + SWO_F) * 4) // 92032 B

typedef unsigned long long u64;

__device__ __forceinline__ u64 dup2(float v) {
    u64 r; asm("mov.b64 %0, {%1, %1};" : "=l"(r) : "f"(v)); return r;
}
__device__ __forceinline__ void ffma2(u64& acc, u64 a, u64 b) {
    asm("fma.rn.f32x2 %0, %1, %2, %0;" : "+l"(acc) : "l"(a), "l"(b));
}
__device__ __forceinline__ void unpk(u64 v, float& lo, float& hi) {
    asm("mov.b64 {%0, %1}, %2;" : "=f"(lo), "=f"(hi) : "l"(v));
}

// tanh(x) = 1 - 2/(e^{2x}+1); e^{2x} = 2^{x*2*log2(e)}.
// ex2.approx (~2ulp) + rcp.approx refined by 1 Newton step => abs err ~1.5e-7.
// Clamp arg at 126 so e stays finite (avoids inf*0 NaN in NR); negative side
// underflows to 0 -> d=1 -> tanh=-1, correct.
__device__ __forceinline__ float tanh_fast(float x) {
    float arg = fminf(x * 2.885390081777927f, 126.0f);
    float e;
    asm("ex2.approx.f32 %0, %1;" : "=f"(e) : "f"(arg));
    float d = e + 1.0f;
    float r;
    asm("rcp.approx.f32 %0, %1;" : "=f"(r) : "f"(d));
    r = r * (2.0f - d * r);              // Newton refine
    return fmaf(-2.0f, r, 1.0f);
}

// sigmoid(x) = 1/(1+e^{-x}); final layer, zero downstream amplification.
__device__ __forceinline__ float sigmoid_fast(float x) {
    float arg = fminf(-x * 1.4426950408889634f, 126.0f);
    float e;
    asm("ex2.approx.f32 %0, %1;" : "=f"(e) : "f"(arg));
    float d = e + 1.0f;
    float r;
    asm("rcp.approx.f32 %0, %1;" : "=f"(r) : "f"(d));
    return r * (2.0f - d * r);
}

template<bool FAST>
__device__ __forceinline__ void hidden_layer(const float* wbase,
                                             float* hA, float* hB) {
    const ulonglong2* w2 = (const ulonglong2*)wbase;   // [k][8] x 16B
    u64 aA[16], aB[16];
    #pragma unroll
    for (int j = 0; j < 16; j++) { aA[j] = 0ull; aB[j] = 0ull; }
    #pragma unroll
    for (int k = 0; k < DH; k++) {
        u64 a2 = dup2(hA[k]), b2 = dup2(hB[k]);
        #pragma unroll
        for (int jj = 0; jj < 8; jj++) {
            ulonglong2 wv = w2[k * 8 + jj];
            ffma2(aA[2 * jj],     a2, wv.x);
            ffma2(aA[2 * jj + 1], a2, wv.y);
            ffma2(aB[2 * jj],     b2, wv.x);
            ffma2(aB[2 * jj + 1], b2, wv.y);
        }
    }
    #pragma unroll
    for (int j = 0; j < 16; j++) {
        float l0, h0; unpk(aA[j], l0, h0);
        float l1, h1; unpk(aB[j], l1, h1);
        if (FAST) {
            hA[2 * j] = tanh_fast(l0); hA[2 * j + 1] = tanh_fast(h0);
            hB[2 * j] = tanh_fast(l1); hB[2 * j + 1] = tanh_fast(h1);
        } else {
            hA[2 * j] = tanhf(l0); hA[2 * j + 1] = tanhf(h0);
            hB[2 * j] = tanhf(l1); hB[2 * j + 1] = tanhf(h1);
        }
    }
}

__global__ void __launch_bounds__(TPB, 1)
cppn_kernel(const float* __restrict__ x,
            const float* __restrict__ W1,
            const float* __restrict__ Wh,
            const float* __restrict__ Wo,
            float* __restrict__ out, int n)
{
    extern __shared__ float sm[];
    float* sWh = sm;                 // [L][k][j], j contiguous
    float* sW1 = sm + SWH_F;         // [k][j]
    float* sWo = sW1 + SW1_F;        // [k][4]  (o = 0..2, o=3 pad)

    for (int idx = threadIdx.x; idx < SWH_F; idx += TPB) {
        int L = idx >> 10, r = idx & 1023, j = r >> 5, k = r & 31;
        sWh[(L << 10) + (k << 5) + j] = Wh[idx];
    }
    for (int idx = threadIdx.x; idx < DH * 11; idx += TPB) {
        int j = idx / 11, k = idx - j * 11;
        sW1[k * DH + j] = W1[idx];
    }
    for (int idx = threadIdx.x; idx < 4 * DH; idx += TPB) {
        int k = idx >> 2, o = idx & 3;
        sWo[idx] = (o < 3) ? Wo[o * DH + k] : 0.0f;
    }
    __syncthreads();

    const int stride = GRID * TPB * 2;
    for (int base = blockIdx.x * (TPB * 2); base < n; base += stride) {
        const int pA = base + (int)threadIdx.x;
        const int pB = pA + TPB;
        const bool vA = (pA < n), vB = (pB < n);

        float hA[DH], hB[DH];

        // ---------------- layer 1: 11 -> 32, accurate tanh ----------------
        {
            float xA[11], xB[11];
            #pragma unroll
            for (int k = 0; k < 11; k++) {
                xA[k] = vA ? x[pA * 11 + k] : 0.0f;
                xB[k] = vB ? x[pB * 11 + k] : 0.0f;
            }
            u64 aA[16], aB[16];
            #pragma unroll
            for (int j = 0; j < 16; j++) { aA[j] = 0ull; aB[j] = 0ull; }
            const ulonglong2* w2 = (const ulonglong2*)sW1;
            #pragma unroll
            for (int k = 0; k < 11; k++) {
                u64 a2 = dup2(xA[k]), b2 = dup2(xB[k]);
                #pragma unroll
                for (int jj = 0; jj < 8; jj++) {
                    ulonglong2 wv = w2[k * 8 + jj];
                    ffma2(aA[2 * jj],     a2, wv.x);
                    ffma2(aA[2 * jj + 1], a2, wv.y);
                    ffma2(aB[2 * jj],     b2, wv.x);
                    ffma2(aB[2 * jj + 1], b2, wv.y);
                }
            }
            #pragma unroll
            for (int j = 0; j < 16; j++) {
                float l0, h0; unpk(aA[j], l0, h0);
                hA[2 * j] = tanhf(l0); hA[2 * j + 1] = tanhf(h0);
                float l1, h1; unpk(aB[j], l1, h1);
                hB[2 * j] = tanhf(l1); hB[2 * j + 1] = tanhf(h1);
            }
        }

        // ------------- hidden 0..2: accurate tanh (high amplification) -----
        #pragma unroll 1
        for (int L = 0; L < NACC; ++L)
            hidden_layer<false>(sWh + (L << 10), hA, hB);

        // ------------- hidden 3..21: fast tanh -----------------------------
        #pragma unroll 1
        for (int L = NACC; L < NHID; ++L)
            hidden_layer<true>(sWh + (L << 10), hA, hB);

        // ---------------- output: 32 -> 3, sigmoid ----------------
        {
            const u64* w = (const u64*)sWo;   // [k][2] u64 per row
            u64 oA0 = 0ull, oA1 = 0ull, oB0 = 0ull, oB1 = 0ull;
            #pragma unroll
            for (int k = 0; k < DH; k++) {
                u64 w0 = w[2 * k], w1 = w[2 * k + 1];
                u64 a2 = dup2(hA[k]), b2 = dup2(hB[k]);
                ffma2(oA0, a2, w0);
                ffma2(oA1, a2, w1);
                ffma2(oB0, b2, w0);
                ffma2(oB1, b2, w1);
            }
            float a0, a1, a2f, adum, b0, b1, b2f, bdum;
            unpk(oA0, a0, a1); unpk(oA1, a2f, adum);
            unpk(oB0, b0, b1); unpk(oB1, b2f, bdum);
            if (vA) {
                out[3 * pA + 0] = sigmoid_fast(a0);
                out[3 * pA + 1] = sigmoid_fast(a1);
                out[3 * pA + 2] = sigmoid_fast(a2f);
            }
            if (vB) {
                out[3 * pB + 0] = sigmoid_fast(b0);
                out[3 * pB + 1] = sigmoid_fast(b1);
                out[3 * pB + 2] = sigmoid_fast(b2f);
            }
        }
    }
}

extern "C" void kernel_launch(void* const* d_in, const int* in_sizes, int n_in,
                              void* d_out, int out_size)
{
    const float* x  = (const float*)d_in[0];
    const float* W1 = (const float*)d_in[1];
    const float* Wh = (const float*)d_in[2];
    const float* Wo = (const float*)d_in[3];
    float* out = (float*)d_out;

    const int n = in_sizes[0] / 11;

    cudaFuncSetAttribute(cppn_kernel,
                         cudaFuncAttributeMaxDynamicSharedMemorySize,
                         SMEM_BYTES);
    cppn_kernel<<<GRID, TPB, SMEM_BYTES>>>(x, W1, Wh, Wo, out, n);
}

// round 9
// speedup vs baseline: 1.0070x; 1.0070x over previous
#include <cuda_runtime.h>
#include <math.h>

// CPPN fused MLP. R7 kernel, third submission (two broker infra failures in a
// row; delta unmeasured). = R3 (proven 5036us) + ONE delta: branch-free fast
// tanh (ex2.approx + NR-refined rcp.approx) for hidden layers 3..21 and the
// output sigmoid. Numerics of this exact math path measured in R6: rel_err
// 2.474e-4. Weight loads stay LDS.64 (u64) exactly as R3 — R6's LDS.128
// variant is the prime suspect for the +1.9e6-cycle stall regression.

#define DH    32
#define NHID  22
#define NACC  3        // hidden layers using accurate tanhf
#define TPB   384
#define GRID  148
#define SWH_F (NHID * DH * DH)                   // 22528
#define SW1_F (11 * DH)                          // 352
#define SWO_F (DH * 4)                           // 128
#define SMEM_BYTES ((SWH_F + SW1_F + SWO_F) * 4) // 92032 B

typedef unsigned long long u64;

__device__ __forceinline__ u64 dup2(float v) {
    u64 r; asm("mov.b64 %0, {%1, %1};" : "=l"(r) : "f"(v)); return r;
}
__device__ __forceinline__ void ffma2(u64& acc, u64 a, u64 b) {
    asm("fma.rn.f32x2 %0, %1, %2, %0;" : "+l"(acc) : "l"(a), "l"(b));
}
__device__ __forceinline__ void unpk(u64 v, float& lo, float& hi) {
    asm("mov.b64 {%0, %1}, %2;" : "=f"(lo), "=f"(hi) : "l"(v));
}

// tanh(x) = 1 - 2/(e^{2x}+1); e^{2x} = 2^{x*2*log2(e)}.
// ex2.approx (~2ulp) + rcp.approx refined by 1 Newton step => abs err ~1.5e-7.
// Clamp arg at 126 so e stays finite; negative side underflows to 0 -> -1.
__device__ __forceinline__ float tanh_fast(float x) {
    float arg = fminf(x * 2.885390081777927f, 126.0f);
    float e;
    asm("ex2.approx.f32 %0, %1;" : "=f"(e) : "f"(arg));
    float d = e + 1.0f;
    float r;
    asm("rcp.approx.f32 %0, %1;" : "=f"(r) : "f"(d));
    r = r * (2.0f - d * r);              // Newton refine
    return fmaf(-2.0f, r, 1.0f);
}

__device__ __forceinline__ float sigmoid_fast(float x) {
    float arg = fminf(-x * 1.4426950408889634f, 126.0f);
    float e;
    asm("ex2.approx.f32 %0, %1;" : "=f"(e) : "f"(arg));
    float d = e + 1.0f;
    float r;
    asm("rcp.approx.f32 %0, %1;" : "=f"(r) : "f"(d));
    return r * (2.0f - d * r);
}

template<bool FAST>
__device__ __forceinline__ void hidden_layer(const float* wbase,
                                             float* hA, float* hB) {
    const u64* w = (const u64*)wbase;    // [k][16] u64, LDS.64 as in R3
    u64 aA[16], aB[16];
    #pragma unroll
    for (int j = 0; j < 16; j++) { aA[j] = 0ull; aB[j] = 0ull; }
    #pragma unroll
    for (int k = 0; k < DH; k++) {
        u64 a2 = dup2(hA[k]), b2 = dup2(hB[k]);
        #pragma unroll
        for (int j = 0; j < 16; j++) {
            u64 wv = w[k * 16 + j];
            ffma2(aA[j], a2, wv);
            ffma2(aB[j], b2, wv);
        }
    }
    #pragma unroll
    for (int j = 0; j < 16; j++) {
        float l0, h0; unpk(aA[j], l0, h0);
        float l1, h1; unpk(aB[j], l1, h1);
        if (FAST) {
            hA[2 * j] = tanh_fast(l0); hA[2 * j + 1] = tanh_fast(h0);
            hB[2 * j] = tanh_fast(l1); hB[2 * j + 1] = tanh_fast(h1);
        } else {
            hA[2 * j] = tanhf(l0); hA[2 * j + 1] = tanhf(h0);
            hB[2 * j] = tanhf(l1); hB[2 * j + 1] = tanhf(h1);
        }
    }
}

__global__ void __launch_bounds__(TPB, 1)
cppn_kernel(const float* __restrict__ x,
            const float* __restrict__ W1,
            const float* __restrict__ Wh,
            const float* __restrict__ Wo,
            float* __restrict__ out, int n)
{
    extern __shared__ float sm[];
    float* sWh = sm;                 // [L][k][j], j contiguous
    float* sW1 = sm + SWH_F;         // [k][j]
    float* sWo = sW1 + SW1_F;        // [k][4]  (o = 0..2, o=3 pad)

    for (int idx = threadIdx.x; idx < SWH_F; idx += TPB) {
        int L = idx >> 10, r = idx & 1023, j = r >> 5, k = r & 31;
        sWh[(L << 10) + (k << 5) + j] = Wh[idx];
    }
    for (int idx = threadIdx.x; idx < DH * 11; idx += TPB) {
        int j = idx / 11, k = idx - j * 11;
        sW1[k * DH + j] = W1[idx];
    }
    for (int idx = threadIdx.x; idx < 4 * DH; idx += TPB) {
        int k = idx >> 2, o = idx & 3;
        sWo[idx] = (o < 3) ? Wo[o * DH + k] : 0.0f;
    }
    __syncthreads();

    const int stride = GRID * TPB * 2;
    for (int base = blockIdx.x * (TPB * 2); base < n; base += stride) {
        const int pA = base + (int)threadIdx.x;
        const int pB = pA + TPB;
        const bool vA = (pA < n), vB = (pB < n);

        float hA[DH], hB[DH];

        // ---------------- layer 1: 11 -> 32, accurate tanh ----------------
        {
            float xA[11], xB[11];
            #pragma unroll
            for (int k = 0; k < 11; k++) {
                xA[k] = vA ? x[pA * 11 + k] : 0.0f;
                xB[k] = vB ? x[pB * 11 + k] : 0.0f;
            }
            u64 aA[16], aB[16];
            #pragma unroll
            for (int j = 0; j < 16; j++) { aA[j] = 0ull; aB[j] = 0ull; }
            const u64* w = (const u64*)sW1;
            #pragma unroll
            for (int k = 0; k < 11; k++) {
                u64 a2 = dup2(xA[k]), b2 = dup2(xB[k]);
                #pragma unroll
                for (int j = 0; j < 16; j++) {
                    u64 wv = w[k * 16 + j];
                    ffma2(aA[j], a2, wv);
                    ffma2(aB[j], b2, wv);
                }
            }
            #pragma unroll
            for (int j = 0; j < 16; j++) {
                float l0, h0; unpk(aA[j], l0, h0);
                hA[2 * j] = tanhf(l0); hA[2 * j + 1] = tanhf(h0);
                float l1, h1; unpk(aB[j], l1, h1);
                hB[2 * j] = tanhf(l1); hB[2 * j + 1] = tanhf(h1);
            }
        }

        // ------------- hidden 0..2: accurate tanh (high amplification) -----
        #pragma unroll 1
        for (int L = 0; L < NACC; ++L)
            hidden_layer<false>(sWh + (L << 10), hA, hB);

        // ------------- hidden 3..21: fast tanh -----------------------------
        #pragma unroll 1
        for (int L = NACC; L < NHID; ++L)
            hidden_layer<true>(sWh + (L << 10), hA, hB);

        // ---------------- output: 32 -> 3, sigmoid ----------------
        {
            const u64* w = (const u64*)sWo;   // [k][2] u64 per row
            u64 oA0 = 0ull, oA1 = 0ull, oB0 = 0ull, oB1 = 0ull;
            #pragma unroll
            for (int k = 0; k < DH; k++) {
                u64 w0 = w[2 * k], w1 = w[2 * k + 1];
                u64 a2 = dup2(hA[k]), b2 = dup2(hB[k]);
                ffma2(oA0, a2, w0);
                ffma2(oA1, a2, w1);
                ffma2(oB0, b2, w0);
                ffma2(oB1, b2, w1);
            }
            float a0, a1, a2f, adum, b0, b1, b2f, bdum;
            unpk(oA0, a0, a1); unpk(oA1, a2f, adum);
            unpk(oB0, b0, b1); unpk(oB1, b2f, bdum);
            if (vA) {
                out[3 * pA + 0] = sigmoid_fast(a0);
                out[3 * pA + 1] = sigmoid_fast(a1);
                out[3 * pA + 2] = sigmoid_fast(a2f);
            }
            if (vB) {
                out[3 * pB + 0] = sigmoid_fast(b0);
                out[3 * pB + 1] = sigmoid_fast(b1);
                out[3 * pB + 2] = sigmoid_fast(b2f);
            }
        }
    }
}

extern "C" void kernel_launch(void* const* d_in, const int* in_sizes, int n_in,
                              void* d_out, int out_size)
{
    const float* x  = (const float*)d_in[0];
    const float* W1 = (const float*)d_in[1];
    const float* Wh = (const float*)d_in[2];
    const float* Wo = (const float*)d_in[3];
    float* out = (float*)d_out;

    const int n = in_sizes[0] / 11;

    cudaFuncSetAttribute(cppn_kernel,
                         cudaFuncAttributeMaxDynamicSharedMemorySize,
                         SMEM_BYTES);
    cppn_kernel<<<GRID, TPB, SMEM_BYTES>>>(x, W1, Wh, Wo, out, n);
}

// round 12
// speedup vs baseline: 1.0320x; 1.0248x over previous
#include <cuda_runtime.h>
#include <math.h>

// CPPN fused MLP. R10 kernel, third submission (broker infra failures; delta
// unmeasured). Math fully reverted to R3 (accurate tanhf everywhere —
// measured: sm_100 tanhf is ~8 instr, MUFU.TANH-based; the ex2/rcp "fast"
// tanh saved no issue slots and added unhidable serial MUFU latency => R6/R9
// regressions). Structural delta vs R3: 1 point/thread @ TPB=640 => 5 warps/
// SMSP (was 3) and ~90 hot regs under a 102 cap, giving ptxas room to
// pipeline the per-k LDS.64 weight batch. Trades +0.755e9 LDS issue slots for
// +67% latency hiding; R3 lost 33% of cycles to all-warps-stalled.

#define DH    32
#define NHID  22
#define TPB   640
#define GRID  148
#define SWH_F (NHID * DH * DH)                   // 22528
#define SW1_F (11 * DH)                          // 352
#define SWO_F (DH * 4)                           // 128
#define SMEM_BYTES ((SWH_F + SW1_F + SWO_F) * 4) // 92032 B

typedef unsigned long long u64;

__device__ __forceinline__ u64 dup2(float v) {
    u64 r; asm("mov.b64 %0, {%1, %1};" : "=l"(r) : "f"(v)); return r;
}
__device__ __forceinline__ void ffma2(u64& acc, u64 a, u64 b) {
    asm("fma.rn.f32x2 %0, %1, %2, %0;" : "+l"(acc) : "l"(a), "l"(b));
}
__device__ __forceinline__ void unpk(u64 v, float& lo, float& hi) {
    asm("mov.b64 {%0, %1}, %2;" : "=f"(lo), "=f"(hi) : "l"(v));
}
__device__ __forceinline__ float sigmoidf_acc(float v) {
    return 1.0f / (1.0f + expf(-v));
}

// One hidden layer for a single point: h = tanh(W * h), W k-major in shared.
__device__ __forceinline__ void hidden_layer(const float* wbase, float* h) {
    const u64* w = (const u64*)wbase;    // [k][16] u64 (broadcast LDS.64)
    u64 a[16];
    #pragma unroll
    for (int j = 0; j < 16; j++) a[j] = 0ull;
    #pragma unroll
    for (int k = 0; k < DH; k++) {
        u64 a2 = dup2(h[k]);
        #pragma unroll
        for (int j = 0; j < 16; j++)
            ffma2(a[j], a2, w[k * 16 + j]);
    }
    #pragma unroll
    for (int j = 0; j < 16; j++) {
        float lo, hi; unpk(a[j], lo, hi);
        h[2 * j] = tanhf(lo);
        h[2 * j + 1] = tanhf(hi);
    }
}

__global__ void __launch_bounds__(TPB, 1)
cppn_kernel(const float* __restrict__ x,
            const float* __restrict__ W1,
            const float* __restrict__ Wh,
            const float* __restrict__ Wo,
            float* __restrict__ out, int n)
{
    extern __shared__ float sm[];
    float* sWh = sm;                 // [L][k][j], j contiguous
    float* sW1 = sm + SWH_F;         // [k][j]
    float* sWo = sW1 + SW1_F;        // [k][4]  (o = 0..2, o=3 pad)

    for (int idx = threadIdx.x; idx < SWH_F; idx += TPB) {
        int L = idx >> 10, r = idx & 1023, j = r >> 5, k = r & 31;
        sWh[(L << 10) + (k << 5) + j] = Wh[idx];
    }
    for (int idx = threadIdx.x; idx < DH * 11; idx += TPB) {
        int j = idx / 11, k = idx - j * 11;
        sW1[k * DH + j] = W1[idx];
    }
    for (int idx = threadIdx.x; idx < 4 * DH; idx += TPB) {
        int k = idx >> 2, o = idx & 3;
        sWo[idx] = (o < 3) ? Wo[o * DH + k] : 0.0f;
    }
    __syncthreads();

    const int stride = GRID * TPB;
    for (int p = blockIdx.x * TPB + (int)threadIdx.x; p < n; p += stride) {
        float h[DH];

        // ---------------- layer 1: 11 -> 32, tanh ----------------
        {
            float xv[11];
            #pragma unroll
            for (int k = 0; k < 11; k++) xv[k] = x[p * 11 + k];
            u64 a[16];
            #pragma unroll
            for (int j = 0; j < 16; j++) a[j] = 0ull;
            const u64* w = (const u64*)sW1;
            #pragma unroll
            for (int k = 0; k < 11; k++) {
                u64 a2 = dup2(xv[k]);
                #pragma unroll
                for (int j = 0; j < 16; j++)
                    ffma2(a[j], a2, w[k * 16 + j]);
            }
            #pragma unroll
            for (int j = 0; j < 16; j++) {
                float lo, hi; unpk(a[j], lo, hi);
                h[2 * j] = tanhf(lo);
                h[2 * j + 1] = tanhf(hi);
            }
        }

        // ---------------- 22 hidden layers: 32 -> 32, tanh ----------------
        #pragma unroll 1
        for (int L = 0; L < NHID; ++L)
            hidden_layer(sWh + (L << 10), h);

        // ---------------- output: 32 -> 3, sigmoid ----------------
        {
            const u64* w = (const u64*)sWo;   // [k][2] u64 per row
            u64 o0 = 0ull, o1 = 0ull;
            #pragma unroll
            for (int k = 0; k < DH; k++) {
                u64 a2 = dup2(h[k]);
                ffma2(o0, a2, w[2 * k]);
                ffma2(o1, a2, w[2 * k + 1]);
            }
            float r0, r1, r2, rpad;
            unpk(o0, r0, r1); unpk(o1, r2, rpad);
            out[3 * p + 0] = sigmoidf_acc(r0);
            out[3 * p + 1] = sigmoidf_acc(r1);
            out[3 * p + 2] = sigmoidf_acc(r2);
        }
    }
}

extern "C" void kernel_launch(void* const* d_in, const int* in_sizes, int n_in,
                              void* d_out, int out_size)
{
    const float* x  = (const float*)d_in[0];
    const float* W1 = (const float*)d_in[1];
    const float* Wh = (const float*)d_in[2];
    const float* Wo = (const float*)d_in[3];
    float* out = (float*)d_out;

    const int n = in_sizes[0] / 11;

    cudaFuncSetAttribute(cppn_kernel,
                         cudaFuncAttributeMaxDynamicSharedMemorySize,
                         SMEM_BYTES);
    cppn_kernel<<<GRID, TPB, SMEM_BYTES>>>(x, W1, Wh, Wo, out, n);
}

// round 13
// speedup vs baseline: 1.0338x; 1.0017x over previous
#include <cuda_runtime.h>
#include <math.h>

// CPPN fused MLP. R13: 1 point/thread + LDS.128 weight loads + TPB=512.
// Evidence chain: fma-busy is invariant ~6.06e6 cyc (the true floor) across
// R3/R6/R9/R12. R12 (1pt, LDS.64, TPB=640) exposed two real constraints:
// L1=89.6% (broadcast-LDS wavefront throughput at the crossbar floor) and
// DRAM=12.8% (register spills under the 102-reg cap). Fix both: LDS.128
// halves smem wavefronts (per-point issue cost becomes identical to R3's
// 2pt+LDS.64), and TPB=512 raises the reg cap to 128 (hot ~95, no spills)
// while keeping 4 warps/SMSP (+33% latency hiding vs R3).
// Math identical to R3: accurate tanhf everywhere + accurate sigmoid.

#define DH    32
#define NHID  22
#define TPB   512
#define GRID  148
#define SWH_F (NHID * DH * DH)                   // 22528
#define SW1_F (11 * DH)                          // 352
#define SWO_F (DH * 4)                           // 128
#define SMEM_BYTES ((SWH_F + SW1_F + SWO_F) * 4) // 92032 B

typedef unsigned long long u64;

__device__ __forceinline__ u64 dup2(float v) {
    u64 r; asm("mov.b64 %0, {%1, %1};" : "=l"(r) : "f"(v)); return r;
}
__device__ __forceinline__ void ffma2(u64& acc, u64 a, u64 b) {
    asm("fma.rn.f32x2 %0, %1, %2, %0;" : "+l"(acc) : "l"(a), "l"(b));
}
__device__ __forceinline__ void unpk(u64 v, float& lo, float& hi) {
    asm("mov.b64 {%0, %1}, %2;" : "=f"(lo), "=f"(hi) : "l"(v));
}
__device__ __forceinline__ float sigmoidf_acc(float v) {
    return 1.0f / (1.0f + expf(-v));
}

// One hidden layer, single point: h = tanh(W * h). W k-major in shared,
// loaded as 16B broadcast LDS.128 (8 per k-step).
__device__ __forceinline__ void hidden_layer(const float* wbase, float* h) {
    const ulonglong2* w2 = (const ulonglong2*)wbase;   // [k][8] x 16B
    u64 a[16];
    #pragma unroll
    for (int j = 0; j < 16; j++) a[j] = 0ull;
    #pragma unroll
    for (int k = 0; k < DH; k++) {
        u64 a2 = dup2(h[k]);
        #pragma unroll
        for (int jj = 0; jj < 8; jj++) {
            ulonglong2 wv = w2[k * 8 + jj];
            ffma2(a[2 * jj],     a2, wv.x);
            ffma2(a[2 * jj + 1], a2, wv.y);
        }
    }
    #pragma unroll
    for (int j = 0; j < 16; j++) {
        float lo, hi; unpk(a[j], lo, hi);
        h[2 * j] = tanhf(lo);
        h[2 * j + 1] = tanhf(hi);
    }
}

__global__ void __launch_bounds__(TPB, 1)
cppn_kernel(const float* __restrict__ x,
            const float* __restrict__ W1,
            const float* __restrict__ Wh,
            const float* __restrict__ Wo,
            float* __restrict__ out, int n)
{
    extern __shared__ float sm[];
    float* sWh = sm;                 // [L][k][j], j contiguous, 16B aligned
    float* sW1 = sm + SWH_F;         // [k][j]
    float* sWo = sW1 + SW1_F;        // [k][4]  (o = 0..2, o=3 pad)

    for (int idx = threadIdx.x; idx < SWH_F; idx += TPB) {
        int L = idx >> 10, r = idx & 1023, j = r >> 5, k = r & 31;
        sWh[(L << 10) + (k << 5) + j] = Wh[idx];
    }
    for (int idx = threadIdx.x; idx < DH * 11; idx += TPB) {
        int j = idx / 11, k = idx - j * 11;
        sW1[k * DH + j] = W1[idx];
    }
    for (int idx = threadIdx.x; idx < 4 * DH; idx += TPB) {
        int k = idx >> 2, o = idx & 3;
        sWo[idx] = (o < 3) ? Wo[o * DH + k] : 0.0f;
    }
    __syncthreads();

    const int stride = GRID * TPB;
    for (int p = blockIdx.x * TPB + (int)threadIdx.x; p < n; p += stride) {
        float h[DH];

        // ---------------- layer 1: 11 -> 32, tanh ----------------
        {
            float xv[11];
            #pragma unroll
            for (int k = 0; k < 11; k++) xv[k] = x[p * 11 + k];
            u64 a[16];
            #pragma unroll
            for (int j = 0; j < 16; j++) a[j] = 0ull;
            const ulonglong2* w2 = (const ulonglong2*)sW1;
            #pragma unroll
            for (int k = 0; k < 11; k++) {
                u64 a2 = dup2(xv[k]);
                #pragma unroll
                for (int jj = 0; jj < 8; jj++) {
                    ulonglong2 wv = w2[k * 8 + jj];
                    ffma2(a[2 * jj],     a2, wv.x);
                    ffma2(a[2 * jj + 1], a2, wv.y);
                }
            }
            #pragma unroll
            for (int j = 0; j < 16; j++) {
                float lo, hi; unpk(a[j], lo, hi);
                h[2 * j] = tanhf(lo);
                h[2 * j + 1] = tanhf(hi);
            }
        }

        // ---------------- 22 hidden layers: 32 -> 32, tanh ----------------
        #pragma unroll 1
        for (int L = 0; L < NHID; ++L)
            hidden_layer(sWh + (L << 10), h);

        // ---------------- output: 32 -> 3, sigmoid ----------------
        {
            const u64* w = (const u64*)sWo;   // [k][2] u64 per row
            u64 o0 = 0ull, o1 = 0ull;
            #pragma unroll
            for (int k = 0; k < DH; k++) {
                u64 a2 = dup2(h[k]);
                ffma2(o0, a2, w[2 * k]);
                ffma2(o1, a2, w[2 * k + 1]);
            }
            float r0, r1, r2, rpad;
            unpk(o0, r0, r1); unpk(o1, r2, rpad);
            out[3 * p + 0] = sigmoidf_acc(r0);
            out[3 * p + 1] = sigmoidf_acc(r1);
            out[3 * p + 2] = sigmoidf_acc(r2);
        }
    }
}

extern "C" void kernel_launch(void* const* d_in, const int* in_sizes, int n_in,
                              void* d_out, int out_size)
{
    const float* x  = (const float*)d_in[0];
    const float* W1 = (const float*)d_in[1];
    const float* Wh = (const float*)d_in[2];
    const float* Wo = (const float*)d_in[3];
    float* out = (float*)d_out;

    const int n = in_sizes[0] / 11;

    cudaFuncSetAttribute(cppn_kernel,
                         cudaFuncAttributeMaxDynamicSharedMemorySize,
                         SMEM_BYTES);
    cppn_kernel<<<GRID, TPB, SMEM_BYTES>>>(x, W1, Wh, Wo, out, n);
}